// round 1
// baseline (speedup 1.0000x reference)
#include <cuda_runtime.h>
#include <math.h>

#define BN 4096
#define KN 3000
#define KPAD 3072
#define CN 8
#define NBLK 148
#define NTHR 1024
#define RPB 28            // ceil(4096/148)
#define LGRP 512          // 4096/8 row-groups for loss kernel

// ---------------- scratch (static __device__, no allocations) ----------------
static __device__ float g_Q[2][(size_t)BN * KN];      // exp matrices, ~98 MB
static __device__ float g_r[2][BN];                   // r = Q @ v
static __device__ float g_u[2][BN];                   // u chain -> final u2
static __device__ float g_v[2][KN];                   // v chain -> final v2
static __device__ float g_cpart[(size_t)NBLK * KPAD]; // column partials
static __device__ unsigned g_err_row;
static __device__ unsigned g_err_col;
static __device__ int g_done;
static __device__ unsigned g_barc = 0;                // grid barrier arrive count
static __device__ unsigned g_barg = 0;                // grid barrier generation
static __device__ float g_rowent[2][BN];
static __device__ float g_rowmaxq[2][BN];
static __device__ float g_losspart[(size_t)CN * LGRP * 3];

struct Args {
    const float* lg[8];
    const int* ia;
    const int* ib;
};

// ---------------- helpers ----------------
__device__ __forceinline__ float warp_max(float v) {
#pragma unroll
    for (int o = 16; o; o >>= 1) v = fmaxf(v, __shfl_xor_sync(0xffffffffu, v, o));
    return v;
}
__device__ __forceinline__ float warp_sum(float v) {
#pragma unroll
    for (int o = 16; o; o >>= 1) v += __shfl_xor_sync(0xffffffffu, v, o);
    return v;
}

// software grid barrier: requires all blocks co-resident (148 blocks, 1 per SM)
__device__ __forceinline__ void gridbar() {
    __syncthreads();
    if (threadIdx.x == 0) {
        __threadfence();
        unsigned gen = *(volatile unsigned*)&g_barg;
        unsigned prev = atomicAdd(&g_barc, 1u);
        if (prev == gridDim.x - 1) {
            g_barc = 0;
            __threadfence();
            atomicAdd(&g_barg, 1u);
        } else {
            while (*(volatile unsigned*)&g_barg == gen) { __nanosleep(32); }
        }
        __threadfence();
    }
    __syncthreads();
}

// ---------------- kernel 1: build Q = exp(x/eps - rowmax), r0 = rowsum ----------------
__global__ void __launch_bounds__(256) buildq_kernel(Args a) {
    const int s = blockIdx.y;
    const int idx = (s == 0) ? *a.ia : *a.ib;
    const float* __restrict__ xr = a.lg[idx] + (size_t)blockIdx.x * KN;
    float* __restrict__ qr = g_Q[s] + (size_t)blockIdx.x * KN;
    __shared__ float sm[8];
    const int tid = threadIdx.x, wid = tid >> 5, lane = tid & 31;

    float m = -3.402823466e38f;
    for (int k = tid; k < KN; k += 256) m = fmaxf(m, xr[k] * 20.0f);
    m = warp_max(m);
    if (lane == 0) sm[wid] = m;
    __syncthreads();
    if (wid == 0) {
        float t = (lane < 8) ? sm[lane] : -3.402823466e38f;
        t = warp_max(t);
        if (lane == 0) sm[0] = t;
    }
    __syncthreads();
    m = sm[0];
    __syncthreads();

    float sum = 0.f;
    for (int k = tid; k < KN; k += 256) {
        float q = expf(xr[k] * 20.0f - m);
        qr[k] = q;
        sum += q;
    }
    sum = warp_sum(sum);
    if (lane == 0) sm[wid] = sum;
    __syncthreads();
    if (wid == 0) {
        float t = (lane < 8) ? sm[lane] : 0.f;
        t = warp_sum(t);
        if (lane == 0) g_r[s][blockIdx.x] = t;
    }
}

// ---------------- kernel 2: persistent double-Sinkhorn with convergence loop ----------------
__global__ void __launch_bounds__(NTHR, 1) sinkhorn_kernel() {
    __shared__ float sv[KN];
    __shared__ float sred[32];
    __shared__ float su[RPB];
    const int tid = threadIdx.x, bi = blockIdx.x;
    const int wid = tid >> 5, lane = tid & 31;
    const float TGT = (float)(4096.0 / 3000.0);

    for (int s = 0; s < 2; s++) {
        float* __restrict__ Q = g_Q[s];
        float* __restrict__ r = g_r[s];
        float* __restrict__ u = g_u[s];
        float* __restrict__ v = g_v[s];

        if (bi == 0 && tid == 0) { g_done = 0; g_err_row = 0u; g_err_col = 0u; }
        gridbar();

        int it = 0;
        while (true) {
            // --- B: u = 1/(r+TINY); column partials c_part = u^T Q (block owns RPB rows)
            {
                const int row0 = bi * RPB;
                const int row1 = min(BN, row0 + RPB);
                if (tid < row1 - row0) {
                    int b = row0 + tid;
                    float ub = 1.0f / (r[b] + 1e-12f);
                    su[tid] = ub;
                    u[b] = ub;
                }
                __syncthreads();
                float a0 = 0.f, a1 = 0.f, a2 = 0.f;
                for (int b = row0; b < row1; b++) {
                    const float ub = su[b - row0];
                    const float* __restrict__ qr = Q + (size_t)b * KN;
                    a0 += ub * qr[tid];
                    a1 += ub * qr[tid + 1024];
                    if (tid < KN - 2048) a2 += ub * qr[tid + 2048];
                }
                float* cp = g_cpart + (size_t)bi * KPAD;
                cp[tid] = a0;
                cp[tid + 1024] = a1;
                if (tid < KN - 2048) cp[tid + 2048] = a2;
            }
            gridbar();
            // --- C: c = sum partials; v = TGT/(c+TINY); col_err = |v*c - TGT|
            {
                float ce = 0.f;
                for (int k = bi * NTHR + tid; k < KN; k += NBLK * NTHR) {
                    float c = 0.f;
#pragma unroll 4
                    for (int i = 0; i < NBLK; i++) c += g_cpart[(size_t)i * KPAD + k];
                    float vk = TGT / (c + 1e-12f);
                    v[k] = vk;
                    ce = fmaxf(ce, fabsf(vk * c - TGT));
                }
                ce = warp_max(ce);
                if (lane == 0) sred[wid] = ce;
                __syncthreads();
                if (wid == 0) {
                    float t = warp_max(sred[lane]);
                    if (lane == 0 && t > 0.f) atomicMax(&g_err_col, __float_as_uint(t));
                }
            }
            gridbar();
            // --- D: r = Q v (warp per row); row_err = |u*r - 1|
            {
                for (int k = tid; k < KN; k += NTHR) sv[k] = v[k];
                __syncthreads();
                const int b = bi * 32 + wid;
                float re = 0.f;
                if (b < BN) {
                    const float* __restrict__ qr = Q + (size_t)b * KN;
                    float acc = 0.f;
#pragma unroll 4
                    for (int k = lane; k < KN; k += 32) acc += qr[k] * sv[k];
                    acc = warp_sum(acc);
                    if (lane == 0) {
                        r[b] = acc;
                        re = fabsf(u[b] * acc - 1.0f);
                    }
                }
                __syncthreads();
                if (lane == 0) sred[wid] = re;
                __syncthreads();
                if (wid == 0) {
                    float t = warp_max(sred[lane]);
                    if (lane == 0 && t > 0.f) atomicMax(&g_err_row, __float_as_uint(t));
                }
            }
            gridbar();
            // --- E: convergence decision (matches reference while_loop semantics)
            it++;
            if (bi == 0 && tid == 0) {
                float er = __uint_as_float(*(volatile unsigned*)&g_err_row);
                float ec = __uint_as_float(*(volatile unsigned*)&g_err_col);
                float err = fmaxf(er, ec);
                g_done = (it >= 3) && ((it >= 100) || (err <= 1e-3f)) ? 1 : 0;
                g_err_row = 0u;
                g_err_col = 0u;
            }
            gridbar();
            if (*(volatile int*)&g_done) break;
        }

        // --- F1: u1 = u/clip(u*r); column partials with u1
        {
            const int row0 = bi * RPB;
            const int row1 = min(BN, row0 + RPB);
            if (tid < row1 - row0) {
                int b = row0 + tid;
                float uo = u[b], rb = r[b];
                float u1v = uo / fmaxf(uo * rb, 1e-12f);
                su[tid] = u1v;
                u[b] = u1v;
            }
            __syncthreads();
            float a0 = 0.f, a1 = 0.f, a2 = 0.f;
            for (int b = row0; b < row1; b++) {
                const float u1v = su[b - row0];
                const float* __restrict__ qr = Q + (size_t)b * KN;
                a0 += u1v * qr[tid];
                a1 += u1v * qr[tid + 1024];
                if (tid < KN - 2048) a2 += u1v * qr[tid + 2048];
            }
            float* cp = g_cpart + (size_t)bi * KPAD;
            cp[tid] = a0;
            cp[tid + 1024] = a1;
            if (tid < KN - 2048) cp[tid + 2048] = a2;
        }
        gridbar();
        // --- F2: v2 = v*TGT/clip(v*c2)
        for (int k = bi * NTHR + tid; k < KN; k += NBLK * NTHR) {
            float c = 0.f;
#pragma unroll 4
            for (int i = 0; i < NBLK; i++) c += g_cpart[(size_t)i * KPAD + k];
            float vk = v[k];
            v[k] = vk * TGT / fmaxf(vk * c, 1e-12f);
        }
        gridbar();
        // --- F3: r2 = Q v2; u2 = u1/clip(u1*r2); entropy + rowmax of final Q
        {
            for (int k = tid; k < KN; k += NTHR) sv[k] = v[k];
            __syncthreads();
            const int b = bi * 32 + wid;
            if (b < BN) {
                const float* __restrict__ qr = Q + (size_t)b * KN;
                float acc = 0.f;
#pragma unroll 4
                for (int k = lane; k < KN; k += 32) acc += qr[k] * sv[k];
                acc = warp_sum(acc);
                float u1v = u[b];
                float u2 = u1v / fmaxf(u1v * acc, 1e-12f);
                float se = 0.f, mq = 0.f;
#pragma unroll 4
                for (int k = lane; k < KN; k += 32) {
                    float q = u2 * qr[k] * sv[k];
                    se += q * logf(q + 1e-12f);
                    mq = fmaxf(mq, q);
                }
                se = warp_sum(se);
                mq = warp_max(mq);
                if (lane == 0) {
                    u[b] = u2;
                    g_rowent[s][b] = se;
                    g_rowmaxq[s][b] = mq;
                }
            }
        }
        gridbar();
    }
}

// ---------------- kernel 3: per-crop logsumexp + dots with final Qa/Qb ----------------
__global__ void __launch_bounds__(256) loss_kernel(Args a) {
    __shared__ float sva[KN];
    __shared__ float svb[KN];
    __shared__ float sm[8];
    __shared__ float s3[24];
    const int tid = threadIdx.x, wid = tid >> 5, lane = tid & 31;
    const int c = blockIdx.y;
    const int ia = *a.ia, ib = *a.ib;
    const bool useA = (c != ia), useB = (c != ib);
    const float* __restrict__ lgp = a.lg[c];

    for (int k = tid; k < KN; k += 256) {
        sva[k] = g_v[0][k];
        svb[k] = g_v[1][k];
    }
    __syncthreads();

    float acc_lse = 0.f, acc_da = 0.f, acc_db = 0.f;
    const int b0 = blockIdx.x * 8;
    for (int rr = 0; rr < 8; rr++) {
        const int b = b0 + rr;
        const float* __restrict__ xr = lgp + (size_t)b * KN;
        const float* __restrict__ qa = g_Q[0] + (size_t)b * KN;
        const float* __restrict__ qb = g_Q[1] + (size_t)b * KN;

        float m = -3.402823466e38f;
        for (int k = tid; k < KN; k += 256) m = fmaxf(m, xr[k]);
        m = warp_max(m);
        if (lane == 0) sm[wid] = m;
        __syncthreads();
        if (wid == 0) {
            float t = (lane < 8) ? sm[lane] : -3.402823466e38f;
            t = warp_max(t);
            if (lane == 0) sm[0] = t;
        }
        __syncthreads();
        m = sm[0];
        __syncthreads();

        float se = 0.f, da = 0.f, db = 0.f;
        for (int k = tid; k < KN; k += 256) {
            float x = xr[k];
            se += expf(10.0f * (x - m));
            if (useA) da += qa[k] * sva[k] * x;
            if (useB) db += qb[k] * svb[k] * x;
        }
        se = warp_sum(se);
        da = warp_sum(da);
        db = warp_sum(db);
        if (lane == 0) { s3[wid] = se; s3[8 + wid] = da; s3[16 + wid] = db; }
        __syncthreads();
        if (tid == 0) {
            float ts = 0.f, ta = 0.f, tb = 0.f;
            for (int w = 0; w < 8; w++) { ts += s3[w]; ta += s3[8 + w]; tb += s3[16 + w]; }
            acc_lse += 10.0f * m + logf(ts);
            acc_da += g_u[0][b] * ta;
            acc_db += g_u[1][b] * tb;
        }
        __syncthreads();
    }
    if (tid == 0) {
        float* p = &g_losspart[((size_t)c * LGRP + blockIdx.x) * 3];
        p[0] = acc_lse;
        p[1] = acc_da;
        p[2] = acc_db;
    }
}

// ---------------- kernel 4: final scalar reduction ----------------
__device__ double bredD(double v, double* sd) {
    const int tid = threadIdx.x, wid = tid >> 5, lane = tid & 31;
#pragma unroll
    for (int o = 16; o; o >>= 1) v += __shfl_xor_sync(0xffffffffu, v, o);
    if (lane == 0) sd[wid] = v;
    __syncthreads();
    double t = 0.0;
    if (wid == 0) {
        t = sd[lane];
#pragma unroll
        for (int o = 16; o; o >>= 1) t += __shfl_xor_sync(0xffffffffu, t, o);
    }
    __syncthreads();
    return t; // valid on tid 0
}

__global__ void __launch_bounds__(1024) fin_kernel(Args a, float* out) {
    __shared__ double sd[32];
    const int tid = threadIdx.x;
    const int ia = *a.ia, ib = *a.ib;
    double se0 = 0, se1 = 0, sm0 = 0, sm1 = 0, sl = 0;
    for (int b = tid; b < BN; b += 1024) {
        se0 += (double)g_rowent[0][b];
        se1 += (double)g_rowent[1][b];
        sm0 += (double)g_rowmaxq[0][b];
        sm1 += (double)g_rowmaxq[1][b];
    }
    for (int i = tid; i < CN * LGRP; i += 1024) {
        int c = i / LGRP;
        const float* p = &g_losspart[(size_t)i * 3];
        double lse = p[0], da = p[1], db = p[2];
        if (c != ia) sl += lse - 10.0 * da;
        if (c != ib) sl += lse - 10.0 * db;
    }
    se0 = bredD(se0, sd);
    se1 = bredD(se1, sd);
    sm0 = bredD(sm0, sd);
    sm1 = bredD(sm1, sd);
    sl = bredD(sl, sd);
    if (tid == 0) {
        double loss = sl / (14.0 * BN);
        double ent = 0.5 * ((-se0 / BN) + (-se1 / BN));
        double qm = 0.5 * ((sm0 + sm1) / BN);
        out[0] = (float)loss;
        out[1] = (float)ent;
        out[2] = (float)qm;
    }
}

// ---------------- entry ----------------
extern "C" void kernel_launch(void* const* d_in, const int* in_sizes, int n_in,
                              void* d_out, int out_size) {
    Args a;
    for (int i = 0; i < 8; i++) a.lg[i] = (const float*)d_in[i];
    a.ia = (const int*)d_in[8];
    a.ib = (const int*)d_in[9];

    buildq_kernel<<<dim3(BN, 2), 256>>>(a);
    sinkhorn_kernel<<<NBLK, NTHR>>>();
    loss_kernel<<<dim3(LGRP, CN), 256>>>(a);
    fin_kernel<<<1, 1024>>>(a, (float*)d_out);
}

// round 4
// speedup vs baseline: 1.2676x; 1.2676x over previous
#include <cuda_runtime.h>
#include <math.h>

#define BN 4096
#define KN 3000
#define KPADC 3072        // padded columns
#define CN 8
#define NBLK 148
#define NTHR 256
#define RPB 28            // ceil(4096/148)
#define CAP 1024          // max nz per row (power of 2)
#define BCAP (RPB*CAP)    // max nz per block
#define COLSP 21          // ceil(3000/148)
#define LGRP 512
#define TOLF 1e-3f
#define THRESH -36.0f
#define FXSCALE 4398046511104.0f       // 2^42
#define FXINV   (1.0f/4398046511104.0f)

typedef unsigned long long ull;

// ---------------- static scratch ----------------
static __device__ unsigned short g_nzi[2][BN][CAP];   // column index per nz
static __device__ float g_nzv[2][BN][CAP];            // exp value per nz
static __device__ float g_nzw[2][BN][CAP];            // final P value per nz
static __device__ int   g_cnt[2][BN];
static __device__ unsigned g_bk[2][NBLK][BCAP];       // packed k | (localrow<<16)
static __device__ float g_bv[2][NBLK][BCAP];
static __device__ int   g_bcnt[2][NBLK];
static __device__ float g_cpart[2][NBLK][KPADC];      // fp32 column partials
static __device__ float g_c[2][KPADC];                // reduced column sums
static __device__ float g_v2[2][KPADC];               // final v
static __device__ float g_r[2][BN];                   // row sums (initial)
static __device__ volatile unsigned g_arrive[NBLK];
static __device__ volatile unsigned g_flagw[4];       // [parity][side]
static __device__ float g_rowent[2][BN];
static __device__ float g_rowmaxq[2][BN];
static __device__ float g_losspart[(size_t)CN * LGRP * 3];

struct Args {
    const float* lg[8];
    const int* ia;
    const int* ib;
};

__device__ __forceinline__ float warp_max(float v) {
#pragma unroll
    for (int o = 16; o; o >>= 1) v = fmaxf(v, __shfl_xor_sync(0xffffffffu, v, o));
    return v;
}
__device__ __forceinline__ float warp_sum(float v) {
#pragma unroll
    for (int o = 16; o; o >>= 1) v += __shfl_xor_sync(0xffffffffu, v, o);
    return v;
}

// ---------------- kernel 1: sparse build (single HBM pass) ----------------
__global__ void __launch_bounds__(256) buildq_kernel(Args a) {
    __shared__ float s_x[KN];
    __shared__ float smx[8];
    __shared__ int s_wc[8], s_woff[8], s_base;

    const int s = blockIdx.y;
    const int row = blockIdx.x;
    const int idx = (s == 0) ? *a.ia : *a.ib;
    const float* __restrict__ xr = a.lg[idx] + (size_t)row * KN;
    const int tid = threadIdx.x, wid = tid >> 5, lane = tid & 31;

    // infra zeroing (once per launch)
    if (blockIdx.x == 0 && s == 0) {
        if (tid < NBLK) g_arrive[tid] = 0u;
        if (tid < 4) g_flagw[tid] = 0u;
    }

    // single global pass: stage + row max
    float m = -3.402823466e38f;
    for (int k = tid; k < KN; k += 256) {
        float x = xr[k];
        s_x[k] = x;
        m = fmaxf(m, x);
    }
    m = warp_max(m);
    if (lane == 0) smx[wid] = m;
    __syncthreads();
    if (wid == 0) {
        float t = (lane < 8) ? smx[lane] : -3.402823466e38f;
        t = warp_max(t);
        if (lane == 0) smx[0] = t;
    }
    if (tid == 0) s_base = 0;
    __syncthreads();
    m = smx[0];

    // deterministic k-ordered compaction from smem
    float rsum = 0.f;
    for (int k0 = 0; k0 < KN; k0 += 256) {
        const int col = k0 + tid;
        bool pred = false;
        float val = 0.f;
        if (col < KN) {
            float d = 20.0f * (s_x[col] - m);
            if (d > THRESH) { pred = true; val = __expf(d); }
        }
        unsigned mask = __ballot_sync(0xffffffffu, pred);
        int wcnt = __popc(mask);
        if (lane == 0) s_wc[wid] = wcnt;
        __syncthreads();
        if (tid == 0) {
            int b = s_base;
#pragma unroll
            for (int w = 0; w < 8; w++) { s_woff[w] = b; b += s_wc[w]; }
            s_base = b;
        }
        __syncthreads();
        if (pred) {
            int pos = s_woff[wid] + __popc(mask & ((1u << lane) - 1u));
            if (pos < CAP) {
                g_nzi[s][row][pos] = (unsigned short)col;
                g_nzv[s][row][pos] = val;
                rsum += val;
            }
        }
        __syncthreads();
    }
    if (tid == 0) g_cnt[s][row] = min(s_base, CAP);

    rsum = warp_sum(rsum);
    if (lane == 0) smx[wid] = rsum;
    __syncthreads();
    if (wid == 0) {
        float t = (lane < 8) ? smx[lane] : 0.f;
        t = warp_sum(t);
        if (lane == 0) g_r[s][row] = t;
    }
}

// ---------------- kernel 1b: block-flattened lists ----------------
__global__ void __launch_bounds__(256) blockify_kernel() {
    const int s = blockIdx.y, bi = blockIdx.x;
    const int tid = threadIdx.x;
    const int row0 = bi * RPB;
    const int nrow = max(0, min(BN, row0 + RPB) - row0);
    __shared__ int s_off[RPB + 1];
    if (tid == 0) {
        int o = 0;
        for (int b = 0; b < nrow; b++) { s_off[b] = o; o += g_cnt[s][row0 + b]; }
        s_off[nrow] = o;
        g_bcnt[s][bi] = o;
    }
    __syncthreads();
    for (int j = tid; j < nrow * CAP; j += 256) {
        int b = j >> 10, i = j & (CAP - 1);
        if (i < g_cnt[s][row0 + b]) {
            int dst = s_off[b] + i;
            g_bk[s][bi][dst] = (unsigned)g_nzi[s][row0 + b][i] | ((unsigned)b << 16);
            g_bv[s][bi][dst] = g_nzv[s][row0 + b][i];
        }
    }
}

// ---------------- kernel 2: persistent sparse double-Sinkhorn ----------------
#define DSMEM_SZ (49152 + 24576 + 1344 + 1024)

__global__ void __launch_bounds__(NTHR, 1) sinkhorn_kernel() {
    extern __shared__ ull dsm[];
    ull* s_c = dsm;                                        // [2][3072] fixed-point scatter
    float* s_v = (float*)(dsm + 2 * KPADC);                // [2][3072]
    float* s_tmp = (float*)(s_v + 2 * KPADC);              // [8*COLSP] cross-warp reduce
    float* s_r = s_tmp + 8 * COLSP + 8;                    // [2][28]
    float* s_u = s_r + 2 * RPB;                            // [2][28]
    float* s_red = s_u + 2 * RPB;                          // [16]
    int* s_cnt = (int*)(s_red + 16);                       // [2][28]

    const int tid = threadIdx.x, bi = blockIdx.x;
    const int wid = tid >> 5, lane = tid & 31;
    const float TGT = (float)(4096.0 / 3000.0);
    const int row0 = bi * RPB;
    const int nrow = max(0, min(BN, row0 + RPB) - row0);
    const int k0 = bi * COLSP;
    unsigned gen = 0;

    for (int j = tid; j < 2 * KPADC; j += NTHR) s_c[j] = 0ull;
    for (int s = 0; s < 2; s++)
        if (tid < nrow) {
            s_r[s * RPB + tid] = g_r[s][row0 + tid];
            s_cnt[s * RPB + tid] = g_cnt[s][row0 + tid];
        }
    __syncthreads();

    bool done0 = false, done1 = false;
    int it = 0;

#define GRIDBAR() do { \
        __syncthreads(); \
        __threadfence(); \
        gen++; \
        if (tid == 0) g_arrive[bi] = gen; \
        if (tid < NBLK) { while (g_arrive[tid] < gen) { __nanosleep(20); } } \
        __syncthreads(); \
        __threadfence(); \
    } while (0)

    while (!(done0 && done1)) {
        const int p = it & 1;
        // --- phase A: u = 1/(r+TINY); fixed-point smem scatter; export fp32 partials ---
        for (int s = 0; s < 2; s++) {
            if (s == 0 ? done0 : done1) continue;
            if (tid < nrow)
                s_u[s * RPB + tid] = 1.0f / (s_r[s * RPB + tid] + 1e-12f);
        }
        __syncthreads();
        for (int s = 0; s < 2; s++) {
            if (s == 0 ? done0 : done1) continue;
            const int bc = g_bcnt[s][bi];
            for (int j = tid; j < bc; j += NTHR) {
                unsigned pk = g_bk[s][bi][j];
                float val = g_bv[s][bi][j];
                float t = s_u[s * RPB + (pk >> 16)] * val;
                atomicAdd(&s_c[s * KPADC + (pk & 0xFFFFu)], __float2ull_rn(t * FXSCALE));
            }
        }
        __syncthreads();
        for (int s = 0; s < 2; s++) {
            if (s == 0 ? done0 : done1) continue;
            for (int j = tid; j < KPADC; j += NTHR) {
                g_cpart[s][bi][j] = (float)s_c[s * KPADC + j] * FXINV;
                s_c[s * KPADC + j] = 0ull;
            }
        }
        GRIDBAR();
        // --- phase B: coalesced owner-column reduce -> c ---
        if (bi == 0 && tid < 2) g_flagw[(p ^ 1) * 2 + tid] = 0u;
        for (int s = 0; s < 2; s++) {
            if (s == 0 ? done0 : done1) continue;
            float facc = 0.f;
            if (lane < COLSP && k0 + lane < KN)
                for (int i = wid; i < NBLK; i += 8) facc += g_cpart[s][i][k0 + lane];
            if (lane < COLSP) s_tmp[wid * COLSP + lane] = facc;
            __syncthreads();
            if (wid == 0 && lane < COLSP && k0 + lane < KN) {
                float t = 0.f;
#pragma unroll
                for (int w = 0; w < 8; w++) t += s_tmp[w * COLSP + lane];
                g_c[s][k0 + lane] = t;
            }
            __syncthreads();
        }
        GRIDBAR();
        // --- phase C: stage v, col err, gather r, row err ---
        {
            float ce0 = 0.f, ce1 = 0.f;
            for (int j = tid; j < 2 * KPADC; j += NTHR) {
                const int s = j / KPADC, k = j % KPADC;
                float v = 0.f;
                if (k < KN && !(s == 0 ? done0 : done1)) {
                    float c = g_c[s][k];
                    v = TGT / (c + 1e-12f);
                    float e = fabsf(v * c - TGT);
                    if (s == 0) ce0 = fmaxf(ce0, e); else ce1 = fmaxf(ce1, e);
                }
                s_v[j] = v;
            }
            ce0 = warp_max(ce0);
            ce1 = warp_max(ce1);
            if (lane == 0) { s_red[wid] = ce0; s_red[8 + wid] = ce1; }
            __syncthreads();
            if (tid == 0) {
                float t0 = 0.f, t1 = 0.f;
                for (int w = 0; w < 8; w++) { t0 = fmaxf(t0, s_red[w]); t1 = fmaxf(t1, s_red[8 + w]); }
                if (t0 > TOLF) g_flagw[p * 2 + 0] = 1u;
                if (t1 > TOLF) g_flagw[p * 2 + 1] = 1u;
            }
            __syncthreads();
        }
        for (int job = wid; job < 2 * RPB; job += 8) {
            const int s = job / RPB, b = job % RPB;
            if ((s == 0 ? done0 : done1) || b >= nrow) continue;
            const int cnt = s_cnt[s * RPB + b];
            float acc = 0.f;
            for (int i = lane; i < cnt; i += 32) {
                int k = g_nzi[s][row0 + b][i];
                acc = fmaf(g_nzv[s][row0 + b][i], s_v[s * KPADC + k], acc);
            }
            acc = warp_sum(acc);
            if (lane == 0) {
                s_r[s * RPB + b] = acc;
                if (fabsf(s_u[s * RPB + b] * acc - 1.0f) > TOLF) g_flagw[p * 2 + s] = 1u;
            }
        }
        GRIDBAR();
        it++;
        if (!done0) done0 = (it >= 3) && ((it >= 100) || (g_flagw[p * 2 + 0] == 0u));
        if (!done1) done1 = (it >= 3) && ((it >= 100) || (g_flagw[p * 2 + 1] == 0u));
    }

    // ---------------- finalize ----------------
    // F1: u1 = u/clip(u*r); scatter with u1
    for (int s = 0; s < 2; s++)
        if (tid < nrow) {
            float u = s_u[s * RPB + tid], r = s_r[s * RPB + tid];
            s_u[s * RPB + tid] = u / fmaxf(u * r, 1e-12f);
        }
    __syncthreads();
    for (int s = 0; s < 2; s++) {
        const int bc = g_bcnt[s][bi];
        for (int j = tid; j < bc; j += NTHR) {
            unsigned pk = g_bk[s][bi][j];
            float val = g_bv[s][bi][j];
            float t = s_u[s * RPB + (pk >> 16)] * val;
            atomicAdd(&s_c[s * KPADC + (pk & 0xFFFFu)], __float2ull_rn(t * FXSCALE));
        }
    }
    __syncthreads();
    for (int j = tid; j < 2 * KPADC; j += NTHR)
        g_cpart[j / KPADC][bi][j % KPADC] = (float)s_c[j] * FXINV;
    GRIDBAR();
    // F2: v2 = v*TGT/clip(v*c2), coalesced owner reduce
    for (int s = 0; s < 2; s++) {
        float facc = 0.f;
        if (lane < COLSP && k0 + lane < KN)
            for (int i = wid; i < NBLK; i += 8) facc += g_cpart[s][i][k0 + lane];
        if (lane < COLSP) s_tmp[wid * COLSP + lane] = facc;
        __syncthreads();
        if (wid == 0 && lane < COLSP && k0 + lane < KN) {
            float c2 = 0.f;
#pragma unroll
            for (int w = 0; w < 8; w++) c2 += s_tmp[w * COLSP + lane];
            float v = TGT / (g_c[s][k0 + lane] + 1e-12f);
            g_v2[s][k0 + lane] = v * TGT / fmaxf(v * c2, 1e-12f);
        }
        __syncthreads();
    }
    GRIDBAR();
    // F3: r2 = Q v2; u2; entropy + rowmax; store w
    for (int j = tid; j < 2 * KPADC; j += NTHR) {
        const int s = j / KPADC, k = j % KPADC;
        s_v[j] = (k < KN) ? g_v2[s][k] : 0.f;
    }
    __syncthreads();
    for (int job = wid; job < 2 * RPB; job += 8) {
        const int s = job / RPB, b = job % RPB;
        if (b >= nrow) continue;
        const int cnt = s_cnt[s * RPB + b];
        float acc = 0.f;
        for (int i = lane; i < cnt; i += 32) {
            int k = g_nzi[s][row0 + b][i];
            acc = fmaf(g_nzv[s][row0 + b][i], s_v[s * KPADC + k], acc);
        }
        acc = warp_sum(acc);
        float u1 = s_u[s * RPB + b];
        float u2 = u1 / fmaxf(u1 * acc, 1e-12f);
        float se = 0.f, mq = 0.f;
        for (int i = lane; i < cnt; i += 32) {
            int k = g_nzi[s][row0 + b][i];
            float w = u2 * g_nzv[s][row0 + b][i] * s_v[s * KPADC + k];
            g_nzw[s][row0 + b][i] = w;
            se = fmaf(w, __logf(w + 1e-12f), se);
            mq = fmaxf(mq, w);
        }
        se = warp_sum(se);
        mq = warp_max(mq);
        if (lane == 0) {
            g_rowent[s][row0 + b] = se;
            g_rowmaxq[s][row0 + b] = mq;
        }
    }
}

// ---------------- kernel 3: loss (single HBM pass, smem-staged rows) ----------------
__global__ void __launch_bounds__(256) loss_kernel(Args a) {
    __shared__ float s_x[KN];
    __shared__ float s_red[8];
    __shared__ float s_ab[2];
    const int tid = threadIdx.x, wid = tid >> 5, lane = tid & 31;
    const int c = blockIdx.y;
    const int ia = *a.ia, ib = *a.ib;
    const bool useA = (c != ia), useB = (c != ib);
    const float* __restrict__ lgp = a.lg[c];

    float acc_lse = 0.f, acc_da = 0.f, acc_db = 0.f;
    const int b0 = blockIdx.x * 8;
    for (int rr = 0; rr < 8; rr++) {
        const int b = b0 + rr;
        const float* __restrict__ xr = lgp + (size_t)b * KN;
        float m = -3.402823466e38f;
        for (int k = tid; k < KN; k += 256) {
            float x = xr[k];
            s_x[k] = x;
            m = fmaxf(m, x);
        }
        m = warp_max(m);
        if (lane == 0) s_red[wid] = m;
        __syncthreads();
        if (wid == 0) {
            float t = (lane < 8) ? s_red[lane] : -3.402823466e38f;
            t = warp_max(t);
            if (lane == 0) s_red[0] = t;
        }
        __syncthreads();
        m = s_red[0];
        __syncthreads();

        float se = 0.f;
        for (int k = tid; k < KN; k += 256) {
            float d = 10.0f * (s_x[k] - m);
            if (d > -18.f) se += __expf(d);
        }
        se = warp_sum(se);
        if (lane == 0) s_red[wid] = se;

        if (wid < 2) {
            const int s = wid;
            float dd = 0.f;
            if (s == 0 ? useA : useB) {
                const int cnt = g_cnt[s][b];
                for (int i = lane; i < cnt; i += 32)
                    dd = fmaf(g_nzw[s][b][i], s_x[(int)g_nzi[s][b][i]], dd);
            }
            dd = warp_sum(dd);
            if (lane == 0) s_ab[s] = dd;
        }
        __syncthreads();
        if (tid == 0) {
            float ts = 0.f;
            for (int w = 0; w < 8; w++) ts += s_red[w];
            acc_lse += 10.0f * m + logf(ts);
            acc_da += s_ab[0];
            acc_db += s_ab[1];
        }
        __syncthreads();
    }
    if (tid == 0) {
        float* p = &g_losspart[((size_t)c * LGRP + blockIdx.x) * 3];
        p[0] = acc_lse;
        p[1] = acc_da;
        p[2] = acc_db;
    }
}

// ---------------- kernel 4: final scalar reduction ----------------
__device__ double bredD(double v, double* sd) {
    const int tid = threadIdx.x, wid = tid >> 5, lane = tid & 31;
#pragma unroll
    for (int o = 16; o; o >>= 1) v += __shfl_xor_sync(0xffffffffu, v, o);
    if (lane == 0) sd[wid] = v;
    __syncthreads();
    double t = 0.0;
    if (wid == 0) {
        t = sd[lane];
#pragma unroll
        for (int o = 16; o; o >>= 1) t += __shfl_xor_sync(0xffffffffu, t, o);
    }
    __syncthreads();
    return t;
}

__global__ void __launch_bounds__(1024) fin_kernel(Args a, float* out) {
    __shared__ double sd[32];
    const int tid = threadIdx.x;
    const int ia = *a.ia, ib = *a.ib;
    double se0 = 0, se1 = 0, sm0 = 0, sm1 = 0, sl = 0;
    for (int b = tid; b < BN; b += 1024) {
        se0 += (double)g_rowent[0][b];
        se1 += (double)g_rowent[1][b];
        sm0 += (double)g_rowmaxq[0][b];
        sm1 += (double)g_rowmaxq[1][b];
    }
    for (int i = tid; i < CN * LGRP; i += 1024) {
        int c = i / LGRP;
        const float* p = &g_losspart[(size_t)i * 3];
        double lse = p[0], da = p[1], db = p[2];
        if (c != ia) sl += lse - 10.0 * da;
        if (c != ib) sl += lse - 10.0 * db;
    }
    se0 = bredD(se0, sd);
    se1 = bredD(se1, sd);
    sm0 = bredD(sm0, sd);
    sm1 = bredD(sm1, sd);
    sl = bredD(sl, sd);
    if (tid == 0) {
        out[0] = (float)(sl / (14.0 * BN));
        out[1] = (float)(0.5 * ((-se0 / BN) + (-se1 / BN)));
        out[2] = (float)(0.5 * ((sm0 + sm1) / BN));
    }
}

// ---------------- entry ----------------
extern "C" void kernel_launch(void* const* d_in, const int* in_sizes, int n_in,
                              void* d_out, int out_size) {
    Args a;
    for (int i = 0; i < 8; i++) a.lg[i] = (const float*)d_in[i];
    a.ia = (const int*)d_in[8];
    a.ib = (const int*)d_in[9];

    cudaFuncSetAttribute(sinkhorn_kernel,
                         cudaFuncAttributeMaxDynamicSharedMemorySize, DSMEM_SZ);

    buildq_kernel<<<dim3(BN, 2), 256>>>(a);
    blockify_kernel<<<dim3(NBLK, 2), 256>>>();
    sinkhorn_kernel<<<NBLK, NTHR, DSMEM_SZ>>>();
    loss_kernel<<<dim3(LGRP, CN), 256>>>(a);
    fin_kernel<<<1, 1024>>>(a, (float*)d_out);
}